// round 2
// baseline (speedup 1.0000x reference)
#include <cuda_runtime.h>
#include <math.h>

// Problem constants
#define B_     2
#define S_     2048
#define HID_   2048
#define NH_    16
#define DQ_    192
#define DNOPE_ 128
#define DROPE_ 64
#define DV_    128
#define RANK_  512
#define M_     (B_*S_)          // 4096 token rows
#define NQ_    (NH_*DQ_)        // 3072
#define NKV_   (NH_*(DNOPE_+DV_)) // 4096
#define CKVW_  (RANK_+DROPE_)   // 576

// Scratch (device globals; no runtime allocation allowed)
__device__ float g_Q  [M_*NQ_];      // q projection, rope applied in place
__device__ float g_CKV[M_*CKVW_];    // kv_a output (c | k_pe raw)
__device__ float g_CLN[M_*RANK_];    // rmsnormed c
__device__ float g_KV [M_*NKV_];     // kv_b output (k_nope | v per head)
__device__ float g_KPE[M_*DROPE_];   // rotated k_pe
__device__ float g_AO [M_*NH_*DV_];  // attention output

// ---------------------------------------------------------------------------
// Generic NT GEMM: C[M][N] = A[M][K] * W[N][K]^T   (all row-major, fp32)
// 64x64 tile, BK=16, 256 threads, 4x4 per thread.
// ---------------------------------------------------------------------------
__global__ void gemm_nt(const float* __restrict__ A, const float* __restrict__ W,
                        float* __restrict__ C, int M, int N, int K) {
    __shared__ float As[16][68];
    __shared__ float Bs[16][68];
    int tid = threadIdx.x;
    int tx = tid & 15, ty = tid >> 4;
    int m0 = blockIdx.y * 64, n0 = blockIdx.x * 64;
    int lrow = tid >> 2;            // 0..63
    int lk   = (tid & 3) * 4;       // 0,4,8,12
    const float* Ap = A + (size_t)(m0 + lrow) * K + lk;
    const float* Wp = W + (size_t)(n0 + lrow) * K + lk;

    float acc[4][4] = {};
    for (int k0 = 0; k0 < K; k0 += 16) {
        float4 av = *(const float4*)(Ap + k0);
        float4 bv = *(const float4*)(Wp + k0);
        __syncthreads();
        As[lk+0][lrow] = av.x; As[lk+1][lrow] = av.y;
        As[lk+2][lrow] = av.z; As[lk+3][lrow] = av.w;
        Bs[lk+0][lrow] = bv.x; Bs[lk+1][lrow] = bv.y;
        Bs[lk+2][lrow] = bv.z; Bs[lk+3][lrow] = bv.w;
        __syncthreads();
        #pragma unroll
        for (int kk = 0; kk < 16; kk++) {
            float4 a4 = *(const float4*)&As[kk][ty*4];
            float4 b4 = *(const float4*)&Bs[kk][tx*4];
            acc[0][0] += a4.x*b4.x; acc[0][1] += a4.x*b4.y; acc[0][2] += a4.x*b4.z; acc[0][3] += a4.x*b4.w;
            acc[1][0] += a4.y*b4.x; acc[1][1] += a4.y*b4.y; acc[1][2] += a4.y*b4.z; acc[1][3] += a4.y*b4.w;
            acc[2][0] += a4.z*b4.x; acc[2][1] += a4.z*b4.y; acc[2][2] += a4.z*b4.z; acc[2][3] += a4.z*b4.w;
            acc[3][0] += a4.w*b4.x; acc[3][1] += a4.w*b4.y; acc[3][2] += a4.w*b4.z; acc[3][3] += a4.w*b4.w;
        }
    }
    #pragma unroll
    for (int i = 0; i < 4; i++) {
        float4 v = make_float4(acc[i][0], acc[i][1], acc[i][2], acc[i][3]);
        *(float4*)&C[(size_t)(m0 + ty*4 + i) * N + n0 + tx*4] = v;
    }
}

// ---------------------------------------------------------------------------
// RMSNorm over first 512 of each 576-wide CKV row, times gamma.
// ---------------------------------------------------------------------------
__global__ void rmsnorm_k(const float* __restrict__ ckv, const float* __restrict__ w,
                          float* __restrict__ out) {
    int m = blockIdx.x;
    int tid = threadIdx.x;   // 128 threads
    const float* row = ckv + (size_t)m * CKVW_;
    float4 v = *(const float4*)(row + tid * 4);
    float ss = v.x*v.x + v.y*v.y + v.z*v.z + v.w*v.w;
    #pragma unroll
    for (int o = 16; o; o >>= 1) ss += __shfl_xor_sync(0xffffffffu, ss, o);
    __shared__ float sacc[4];
    if ((tid & 31) == 0) sacc[tid >> 5] = ss;
    __syncthreads();
    float tot = sacc[0] + sacc[1] + sacc[2] + sacc[3];
    float inv = rsqrtf(tot * (1.0f/512.0f) + 1e-6f);
    float4 wv = *(const float4*)(w + tid * 4);
    float4 o4 = make_float4(v.x*inv*wv.x, v.y*inv*wv.y, v.z*inv*wv.z, v.w*inv*wv.w);
    *(float4*)(out + (size_t)m * RANK_ + tid * 4) = o4;
}

// ---------------------------------------------------------------------------
// YaRN rope. inv_freq per half-dim j (0..31). For the given constants:
// corr_dim(32)=10.47 -> low=10, corr_dim(1)=22.51 -> high=23, mscale ratio = 1.
// Deinterleave+rotate fused: pair (x[2k], x[2k+1]) -> slots k, k+32:
//   y[k]    = x0*cos - x1*sin
//   y[k+32] = x1*cos + x0*sin
// Position for token row m is m % S_ (reference positions are tile(arange(S))).
// This avoids the int64-vs-int32 dtype ambiguity of the position_ids input.
// ---------------------------------------------------------------------------
__device__ __forceinline__ float yarn_inv_freq(int j) {
    float fe = powf(10000.0f, -(float)(2*j) / 64.0f);
    float fi = fe * (1.0f / 40.0f);
    float ramp = fminf(fmaxf(((float)j - 10.0f) * (1.0f/13.0f), 0.0f), 1.0f);
    return fi * ramp + fe * (1.0f - ramp);
}

__global__ void rope_q(float* __restrict__ Q) {
    int warp = (blockIdx.x * blockDim.x + threadIdx.x) >> 5;  // (m,h) vector id
    int lane = threadIdx.x & 31;
    int m = warp >> 4, h = warp & 15;
    float* p = Q + (size_t)m * NQ_ + h * DQ_ + DNOPE_;
    float x0 = p[2*lane], x1 = p[2*lane+1];
    float ang = (float)(m % S_) * yarn_inv_freq(lane);
    float s, c;
    sincosf(ang, &s, &c);
    float y0 = x0*c - x1*s;
    float y1 = x1*c + x0*s;
    __syncwarp();
    p[lane]      = y0;
    p[lane + 32] = y1;
}

__global__ void rope_k(const float* __restrict__ ckv, float* __restrict__ kpe) {
    int warp = (blockIdx.x * blockDim.x + threadIdx.x) >> 5;  // m
    int lane = threadIdx.x & 31;
    const float* p = ckv + (size_t)warp * CKVW_ + RANK_;
    float x0 = p[2*lane], x1 = p[2*lane+1];
    float ang = (float)(warp % S_) * yarn_inv_freq(lane);
    float s, c;
    sincosf(ang, &s, &c);
    kpe[(size_t)warp * DROPE_ + lane]      = x0*c - x1*s;
    kpe[(size_t)warp * DROPE_ + lane + 32] = x1*c + x0*s;
}

// ---------------------------------------------------------------------------
// Flash attention, fp32. One block = (b, h, 64-query tile). 256 threads.
// Score tile 64x64, 4x4 per thread. Smem K/Q stored d-major [192][68] so the
// inner product loop reads row-contiguous float4 (conflict-free).
// ---------------------------------------------------------------------------
#define SQK 68
#define ATTN_SMEM ((2*192*SQK + 64*128 + 64*SQK) * sizeof(float))  // 154624 B

__global__ void attn_kernel(const float* __restrict__ Q, const float* __restrict__ KV,
                            const float* __restrict__ KPE, float* __restrict__ AO) {
    extern __shared__ float sm[];
    float* Qs = sm;                 // [192][SQK]
    float* Ks = Qs + 192*SQK;       // [192][SQK]
    float* Vs = Ks + 192*SQK;       // [64][128]
    float* Ps = Vs + 64*128;        // [64][SQK]

    int tid = threadIdx.x;
    int tx = tid & 15, ty = tid >> 4;
    int qt = gridDim.x - 1 - blockIdx.x;   // reverse: heavy tiles first
    int h  = blockIdx.y, b = blockIdx.z;
    int q0 = qt * 64;
    const size_t base = (size_t)b * S_;

    // Load Q tile (transpose to d-major)
    for (int idx = tid; idx < 64*48; idx += 256) {
        int r = idx / 48, d4 = idx % 48;
        float4 v = *(const float4*)(Q + (base + q0 + r) * NQ_ + h * DQ_ + d4*4);
        Qs[(d4*4+0)*SQK + r] = v.x;
        Qs[(d4*4+1)*SQK + r] = v.y;
        Qs[(d4*4+2)*SQK + r] = v.z;
        Qs[(d4*4+3)*SQK + r] = v.w;
    }

    float m_r[4], l_r[4], o[4][8];
    #pragma unroll
    for (int i = 0; i < 4; i++) {
        m_r[i] = -INFINITY; l_r[i] = 0.0f;
        #pragma unroll
        for (int j = 0; j < 8; j++) o[i][j] = 0.0f;
    }
    __syncthreads();

    const float scale = 0.072168784f;   // 1/sqrt(192)
    int ktiles = q0/64 + 1;

    for (int kt = 0; kt < ktiles; kt++) {
        int k0 = kt * 64;
        __syncthreads();   // protect Ks/Vs/Ps reuse
        // K tile: d<128 from KV (k_nope), d>=128 from KPE; transpose to d-major
        for (int idx = tid; idx < 64*48; idx += 256) {
            int r = idx / 48, d4 = idx % 48;
            float4 v;
            if (d4 < 32)
                v = *(const float4*)(KV + (base + k0 + r) * NKV_ + h*256 + d4*4);
            else
                v = *(const float4*)(KPE + (base + k0 + r) * DROPE_ + (d4-32)*4);
            Ks[(d4*4+0)*SQK + r] = v.x;
            Ks[(d4*4+1)*SQK + r] = v.y;
            Ks[(d4*4+2)*SQK + r] = v.z;
            Ks[(d4*4+3)*SQK + r] = v.w;
        }
        // V tile [64][128]
        for (int idx = tid; idx < 64*32; idx += 256) {
            int r = idx / 32, d4 = idx % 32;
            *(float4*)&Vs[r*128 + d4*4] =
                *(const float4*)(KV + (base + k0 + r) * NKV_ + h*256 + 128 + d4*4);
        }
        __syncthreads();

        // scores
        float acc[4][4] = {};
        #pragma unroll 8
        for (int d = 0; d < 192; d++) {
            float4 a4 = *(const float4*)&Qs[d*SQK + ty*4];
            float4 b4 = *(const float4*)&Ks[d*SQK + tx*4];
            acc[0][0] += a4.x*b4.x; acc[0][1] += a4.x*b4.y; acc[0][2] += a4.x*b4.z; acc[0][3] += a4.x*b4.w;
            acc[1][0] += a4.y*b4.x; acc[1][1] += a4.y*b4.y; acc[1][2] += a4.y*b4.z; acc[1][3] += a4.y*b4.w;
            acc[2][0] += a4.z*b4.x; acc[2][1] += a4.z*b4.y; acc[2][2] += a4.z*b4.z; acc[2][3] += a4.z*b4.w;
            acc[3][0] += a4.w*b4.x; acc[3][1] += a4.w*b4.y; acc[3][2] += a4.w*b4.z; acc[3][3] += a4.w*b4.w;
        }
        // scale + causal mask
        #pragma unroll
        for (int i = 0; i < 4; i++)
            #pragma unroll
            for (int j = 0; j < 4; j++) {
                float v = acc[i][j] * scale;
                if (k0 + tx*4 + j > q0 + ty*4 + i) v = -1e30f;
                acc[i][j] = v;
            }
        // online softmax (row groups = 16 consecutive lanes)
        #pragma unroll
        for (int i = 0; i < 4; i++) {
            float tm = fmaxf(fmaxf(acc[i][0], acc[i][1]), fmaxf(acc[i][2], acc[i][3]));
            #pragma unroll
            for (int msk = 8; msk; msk >>= 1)
                tm = fmaxf(tm, __shfl_xor_sync(0xffffffffu, tm, msk, 16));
            float nm = fmaxf(m_r[i], tm);
            float corr = expf(m_r[i] - nm);
            float rs = 0.0f;
            #pragma unroll
            for (int j = 0; j < 4; j++) {
                float p = expf(acc[i][j] - nm);
                Ps[(ty*4+i)*SQK + tx*4 + j] = p;
                rs += p;
            }
            #pragma unroll
            for (int msk = 8; msk; msk >>= 1)
                rs += __shfl_xor_sync(0xffffffffu, rs, msk, 16);
            l_r[i] = l_r[i] * corr + rs;
            m_r[i] = nm;
            #pragma unroll
            for (int j = 0; j < 8; j++) o[i][j] *= corr;
        }
        __syncwarp();   // Ps rows are produced/consumed within the same warp
        // O += P @ V  (cols tx*8 .. tx*8+7)
        #pragma unroll 4
        for (int kk = 0; kk < 64; kk++) {
            float4 v0 = *(const float4*)&Vs[kk*128 + tx*8];
            float4 v1 = *(const float4*)&Vs[kk*128 + tx*8 + 4];
            #pragma unroll
            for (int i = 0; i < 4; i++) {
                float p = Ps[(ty*4+i)*SQK + kk];
                o[i][0] += p*v0.x; o[i][1] += p*v0.y; o[i][2] += p*v0.z; o[i][3] += p*v0.w;
                o[i][4] += p*v1.x; o[i][5] += p*v1.y; o[i][6] += p*v1.z; o[i][7] += p*v1.w;
            }
        }
    }

    // epilogue: normalize and write AO[b,q,h*128+c]
    #pragma unroll
    for (int i = 0; i < 4; i++) {
        float invl = 1.0f / l_r[i];
        float4 w0 = make_float4(o[i][0]*invl, o[i][1]*invl, o[i][2]*invl, o[i][3]*invl);
        float4 w1 = make_float4(o[i][4]*invl, o[i][5]*invl, o[i][6]*invl, o[i][7]*invl);
        size_t row = (base + q0 + ty*4 + i) * (size_t)(NH_*DV_) + h*DV_ + tx*8;
        *(float4*)&AO[row]     = w0;
        *(float4*)&AO[row + 4] = w1;
    }
}

// ---------------------------------------------------------------------------
extern "C" void kernel_launch(void* const* d_in, const int* in_sizes, int n_in,
                              void* d_out, int out_size) {
    const float*     hidden = (const float*)d_in[0];
    const float*     q_w    = (const float*)d_in[2];
    const float*     kv_a_w = (const float*)d_in[3];
    const float*     ln_w   = (const float*)d_in[4];
    const float*     kv_b_w = (const float*)d_in[5];
    const float*     o_w    = (const float*)d_in[6];
    float*           out    = (float*)d_out;

    float *pQ, *pCKV, *pCLN, *pKV, *pKPE, *pAO;
    cudaGetSymbolAddress((void**)&pQ,   g_Q);
    cudaGetSymbolAddress((void**)&pCKV, g_CKV);
    cudaGetSymbolAddress((void**)&pCLN, g_CLN);
    cudaGetSymbolAddress((void**)&pKV,  g_KV);
    cudaGetSymbolAddress((void**)&pKPE, g_KPE);
    cudaGetSymbolAddress((void**)&pAO,  g_AO);

    cudaFuncSetAttribute(attn_kernel, cudaFuncAttributeMaxDynamicSharedMemorySize,
                         (int)ATTN_SMEM);

    dim3 blk(256);
    // 1. Q projection: [4096,2048] x [3072,2048]^T
    gemm_nt<<<dim3(NQ_/64, M_/64), blk>>>(hidden, q_w, pQ, M_, NQ_, HID_);
    // 2. KV-A projection: [4096,2048] x [576,2048]^T
    gemm_nt<<<dim3(CKVW_/64, M_/64), blk>>>(hidden, kv_a_w, pCKV, M_, CKVW_, HID_);
    // 3. RMSNorm on c
    rmsnorm_k<<<M_, 128>>>(pCKV, ln_w, pCLN);
    // 4. KV-B projection: [4096,512] x [4096,512]^T
    gemm_nt<<<dim3(NKV_/64, M_/64), blk>>>(pCLN, kv_b_w, pKV, M_, NKV_, RANK_);
    // 5/6. RoPE
    rope_q<<<(M_*NH_)/8, 256>>>(pQ);      // 8 warps/block, one (m,h) per warp
    rope_k<<<M_/8, 256>>>(pCKV, pKPE);
    // 7. Attention
    attn_kernel<<<dim3(S_/64, NH_, B_), blk, ATTN_SMEM>>>(pQ, pKV, pKPE, pAO);
    // 8. Output projection -> d_out
    gemm_nt<<<dim3(HID_/64, M_/64), blk>>>(pAO, o_w, out, M_, HID_, HID_);
}

// round 3
// speedup vs baseline: 1.0017x; 1.0017x over previous
#include <cuda_runtime.h>
#include <math.h>

// Problem constants
#define B_     2
#define S_     2048
#define HID_   2048
#define NH_    16
#define DQ_    192
#define DNOPE_ 128
#define DROPE_ 64
#define DV_    128
#define RANK_  512
#define M_     (B_*S_)          // 4096 token rows
#define NQ_    (NH_*DQ_)        // 3072
#define NKV_   (NH_*(DNOPE_+DV_)) // 4096
#define CKVW_  (RANK_+DROPE_)   // 576

// Scratch (device globals; no runtime allocation allowed)
__device__ float g_Q  [M_*NQ_];      // q projection, rope applied in place
__device__ float g_CKV[M_*CKVW_];    // kv_a output (c | k_pe raw)
__device__ float g_CLN[M_*RANK_];    // rmsnormed c
__device__ float g_KV [M_*NKV_];     // kv_b output (k_nope | v per head)
__device__ float g_KPE[M_*DROPE_];   // rotated k_pe
__device__ float g_AO [M_*NH_*DV_];  // attention output

// ---------------------------------------------------------------------------
// Generic NT GEMM: C[M][N] = A[M][K] * W[N][K]^T   (all row-major, fp32)
// 64x64 tile, BK=16, 256 threads, 4x4 per thread.
// ---------------------------------------------------------------------------
__global__ void gemm_nt(const float* __restrict__ A, const float* __restrict__ W,
                        float* __restrict__ C, int M, int N, int K) {
    __shared__ float As[16][68];
    __shared__ float Bs[16][68];
    int tid = threadIdx.x;
    int tx = tid & 15, ty = tid >> 4;
    int m0 = blockIdx.y * 64, n0 = blockIdx.x * 64;
    int lrow = tid >> 2;            // 0..63
    int lk   = (tid & 3) * 4;       // 0,4,8,12
    const float* Ap = A + (size_t)(m0 + lrow) * K + lk;
    const float* Wp = W + (size_t)(n0 + lrow) * K + lk;

    float acc[4][4] = {};
    for (int k0 = 0; k0 < K; k0 += 16) {
        float4 av = *(const float4*)(Ap + k0);
        float4 bv = *(const float4*)(Wp + k0);
        __syncthreads();
        As[lk+0][lrow] = av.x; As[lk+1][lrow] = av.y;
        As[lk+2][lrow] = av.z; As[lk+3][lrow] = av.w;
        Bs[lk+0][lrow] = bv.x; Bs[lk+1][lrow] = bv.y;
        Bs[lk+2][lrow] = bv.z; Bs[lk+3][lrow] = bv.w;
        __syncthreads();
        #pragma unroll
        for (int kk = 0; kk < 16; kk++) {
            float4 a4 = *(const float4*)&As[kk][ty*4];
            float4 b4 = *(const float4*)&Bs[kk][tx*4];
            acc[0][0] += a4.x*b4.x; acc[0][1] += a4.x*b4.y; acc[0][2] += a4.x*b4.z; acc[0][3] += a4.x*b4.w;
            acc[1][0] += a4.y*b4.x; acc[1][1] += a4.y*b4.y; acc[1][2] += a4.y*b4.z; acc[1][3] += a4.y*b4.w;
            acc[2][0] += a4.z*b4.x; acc[2][1] += a4.z*b4.y; acc[2][2] += a4.z*b4.z; acc[2][3] += a4.z*b4.w;
            acc[3][0] += a4.w*b4.x; acc[3][1] += a4.w*b4.y; acc[3][2] += a4.w*b4.z; acc[3][3] += a4.w*b4.w;
        }
    }
    #pragma unroll
    for (int i = 0; i < 4; i++) {
        float4 v = make_float4(acc[i][0], acc[i][1], acc[i][2], acc[i][3]);
        *(float4*)&C[(size_t)(m0 + ty*4 + i) * N + n0 + tx*4] = v;
    }
}

// ---------------------------------------------------------------------------
// RMSNorm over first 512 of each 576-wide CKV row, times gamma.
// ---------------------------------------------------------------------------
__global__ void rmsnorm_k(const float* __restrict__ ckv, const float* __restrict__ w,
                          float* __restrict__ out) {
    int m = blockIdx.x;
    int tid = threadIdx.x;   // 128 threads
    const float* row = ckv + (size_t)m * CKVW_;
    float4 v = *(const float4*)(row + tid * 4);
    float ss = v.x*v.x + v.y*v.y + v.z*v.z + v.w*v.w;
    #pragma unroll
    for (int o = 16; o; o >>= 1) ss += __shfl_xor_sync(0xffffffffu, ss, o);
    __shared__ float sacc[4];
    if ((tid & 31) == 0) sacc[tid >> 5] = ss;
    __syncthreads();
    float tot = sacc[0] + sacc[1] + sacc[2] + sacc[3];
    float inv = rsqrtf(tot * (1.0f/512.0f) + 1e-6f);
    float4 wv = *(const float4*)(w + tid * 4);
    float4 o4 = make_float4(v.x*inv*wv.x, v.y*inv*wv.y, v.z*inv*wv.z, v.w*inv*wv.w);
    *(float4*)(out + (size_t)m * RANK_ + tid * 4) = o4;
}

// ---------------------------------------------------------------------------
// YaRN rope. inv_freq per half-dim j (0..31). For the given constants:
// corr_dim(32)=10.47 -> low=10, corr_dim(1)=22.51 -> high=23, mscale ratio = 1.
// Deinterleave+rotate fused: pair (x[2k], x[2k+1]) -> slots k, k+32:
//   y[k]    = x0*cos - x1*sin
//   y[k+32] = x1*cos + x0*sin
// Position for token row m is m % S_ (reference positions are tile(arange(S))).
// This avoids the int64-vs-int32 dtype ambiguity of the position_ids input.
// ---------------------------------------------------------------------------
__device__ __forceinline__ float yarn_inv_freq(int j) {
    float fe = powf(10000.0f, -(float)(2*j) / 64.0f);
    float fi = fe * (1.0f / 40.0f);
    float ramp = fminf(fmaxf(((float)j - 10.0f) * (1.0f/13.0f), 0.0f), 1.0f);
    return fi * ramp + fe * (1.0f - ramp);
}

__global__ void rope_q(float* __restrict__ Q) {
    int warp = (blockIdx.x * blockDim.x + threadIdx.x) >> 5;  // (m,h) vector id
    int lane = threadIdx.x & 31;
    int m = warp >> 4, h = warp & 15;
    float* p = Q + (size_t)m * NQ_ + h * DQ_ + DNOPE_;
    float x0 = p[2*lane], x1 = p[2*lane+1];
    float ang = (float)(m % S_) * yarn_inv_freq(lane);
    float s, c;
    sincosf(ang, &s, &c);
    float y0 = x0*c - x1*s;
    float y1 = x1*c + x0*s;
    __syncwarp();
    p[lane]      = y0;
    p[lane + 32] = y1;
}

__global__ void rope_k(const float* __restrict__ ckv, float* __restrict__ kpe) {
    int warp = (blockIdx.x * blockDim.x + threadIdx.x) >> 5;  // m
    int lane = threadIdx.x & 31;
    const float* p = ckv + (size_t)warp * CKVW_ + RANK_;
    float x0 = p[2*lane], x1 = p[2*lane+1];
    float ang = (float)(warp % S_) * yarn_inv_freq(lane);
    float s, c;
    sincosf(ang, &s, &c);
    kpe[(size_t)warp * DROPE_ + lane]      = x0*c - x1*s;
    kpe[(size_t)warp * DROPE_ + lane + 32] = x1*c + x0*s;
}

// ---------------------------------------------------------------------------
// Flash attention, fp32. One block = (b, h, 64-query tile). 256 threads.
// Score tile 64x64, 4x4 per thread. Smem K/Q stored d-major [192][68] so the
// inner product loop reads row-contiguous float4 (conflict-free).
// ---------------------------------------------------------------------------
#define SQK 68
#define ATTN_SMEM ((2*192*SQK + 64*128 + 64*SQK) * sizeof(float))  // 154624 B

__global__ void attn_kernel(const float* __restrict__ Q, const float* __restrict__ KV,
                            const float* __restrict__ KPE, float* __restrict__ AO) {
    extern __shared__ float sm[];
    float* Qs = sm;                 // [192][SQK]
    float* Ks = Qs + 192*SQK;       // [192][SQK]
    float* Vs = Ks + 192*SQK;       // [64][128]
    float* Ps = Vs + 64*128;        // [64][SQK]

    int tid = threadIdx.x;
    int tx = tid & 15, ty = tid >> 4;
    int qt = gridDim.x - 1 - blockIdx.x;   // reverse: heavy tiles first
    int h  = blockIdx.y, b = blockIdx.z;
    int q0 = qt * 64;
    const size_t base = (size_t)b * S_;

    // Load Q tile (transpose to d-major)
    for (int idx = tid; idx < 64*48; idx += 256) {
        int r = idx / 48, d4 = idx % 48;
        float4 v = *(const float4*)(Q + (base + q0 + r) * NQ_ + h * DQ_ + d4*4);
        Qs[(d4*4+0)*SQK + r] = v.x;
        Qs[(d4*4+1)*SQK + r] = v.y;
        Qs[(d4*4+2)*SQK + r] = v.z;
        Qs[(d4*4+3)*SQK + r] = v.w;
    }

    float m_r[4], l_r[4], o[4][8];
    #pragma unroll
    for (int i = 0; i < 4; i++) {
        m_r[i] = -INFINITY; l_r[i] = 0.0f;
        #pragma unroll
        for (int j = 0; j < 8; j++) o[i][j] = 0.0f;
    }
    __syncthreads();

    const float scale = 0.072168784f;   // 1/sqrt(192)
    int ktiles = q0/64 + 1;

    for (int kt = 0; kt < ktiles; kt++) {
        int k0 = kt * 64;
        __syncthreads();   // protect Ks/Vs/Ps reuse
        // K tile: d<128 from KV (k_nope), d>=128 from KPE; transpose to d-major
        for (int idx = tid; idx < 64*48; idx += 256) {
            int r = idx / 48, d4 = idx % 48;
            float4 v;
            if (d4 < 32)
                v = *(const float4*)(KV + (base + k0 + r) * NKV_ + h*256 + d4*4);
            else
                v = *(const float4*)(KPE + (base + k0 + r) * DROPE_ + (d4-32)*4);
            Ks[(d4*4+0)*SQK + r] = v.x;
            Ks[(d4*4+1)*SQK + r] = v.y;
            Ks[(d4*4+2)*SQK + r] = v.z;
            Ks[(d4*4+3)*SQK + r] = v.w;
        }
        // V tile [64][128]
        for (int idx = tid; idx < 64*32; idx += 256) {
            int r = idx / 32, d4 = idx % 32;
            *(float4*)&Vs[r*128 + d4*4] =
                *(const float4*)(KV + (base + k0 + r) * NKV_ + h*256 + 128 + d4*4);
        }
        __syncthreads();

        // scores
        float acc[4][4] = {};
        #pragma unroll 8
        for (int d = 0; d < 192; d++) {
            float4 a4 = *(const float4*)&Qs[d*SQK + ty*4];
            float4 b4 = *(const float4*)&Ks[d*SQK + tx*4];
            acc[0][0] += a4.x*b4.x; acc[0][1] += a4.x*b4.y; acc[0][2] += a4.x*b4.z; acc[0][3] += a4.x*b4.w;
            acc[1][0] += a4.y*b4.x; acc[1][1] += a4.y*b4.y; acc[1][2] += a4.y*b4.z; acc[1][3] += a4.y*b4.w;
            acc[2][0] += a4.z*b4.x; acc[2][1] += a4.z*b4.y; acc[2][2] += a4.z*b4.z; acc[2][3] += a4.z*b4.w;
            acc[3][0] += a4.w*b4.x; acc[3][1] += a4.w*b4.y; acc[3][2] += a4.w*b4.z; acc[3][3] += a4.w*b4.w;
        }
        // scale + causal mask
        #pragma unroll
        for (int i = 0; i < 4; i++)
            #pragma unroll
            for (int j = 0; j < 4; j++) {
                float v = acc[i][j] * scale;
                if (k0 + tx*4 + j > q0 + ty*4 + i) v = -1e30f;
                acc[i][j] = v;
            }
        // online softmax (row groups = 16 consecutive lanes)
        #pragma unroll
        for (int i = 0; i < 4; i++) {
            float tm = fmaxf(fmaxf(acc[i][0], acc[i][1]), fmaxf(acc[i][2], acc[i][3]));
            #pragma unroll
            for (int msk = 8; msk; msk >>= 1)
                tm = fmaxf(tm, __shfl_xor_sync(0xffffffffu, tm, msk, 16));
            float nm = fmaxf(m_r[i], tm);
            float corr = expf(m_r[i] - nm);
            float rs = 0.0f;
            #pragma unroll
            for (int j = 0; j < 4; j++) {
                float p = expf(acc[i][j] - nm);
                Ps[(ty*4+i)*SQK + tx*4 + j] = p;
                rs += p;
            }
            #pragma unroll
            for (int msk = 8; msk; msk >>= 1)
                rs += __shfl_xor_sync(0xffffffffu, rs, msk, 16);
            l_r[i] = l_r[i] * corr + rs;
            m_r[i] = nm;
            #pragma unroll
            for (int j = 0; j < 8; j++) o[i][j] *= corr;
        }
        __syncwarp();   // Ps rows are produced/consumed within the same warp
        // O += P @ V  (cols tx*8 .. tx*8+7)
        #pragma unroll 4
        for (int kk = 0; kk < 64; kk++) {
            float4 v0 = *(const float4*)&Vs[kk*128 + tx*8];
            float4 v1 = *(const float4*)&Vs[kk*128 + tx*8 + 4];
            #pragma unroll
            for (int i = 0; i < 4; i++) {
                float p = Ps[(ty*4+i)*SQK + kk];
                o[i][0] += p*v0.x; o[i][1] += p*v0.y; o[i][2] += p*v0.z; o[i][3] += p*v0.w;
                o[i][4] += p*v1.x; o[i][5] += p*v1.y; o[i][6] += p*v1.z; o[i][7] += p*v1.w;
            }
        }
    }

    // epilogue: normalize and write AO[b,q,h*128+c]
    #pragma unroll
    for (int i = 0; i < 4; i++) {
        float invl = 1.0f / l_r[i];
        float4 w0 = make_float4(o[i][0]*invl, o[i][1]*invl, o[i][2]*invl, o[i][3]*invl);
        float4 w1 = make_float4(o[i][4]*invl, o[i][5]*invl, o[i][6]*invl, o[i][7]*invl);
        size_t row = (base + q0 + ty*4 + i) * (size_t)(NH_*DV_) + h*DV_ + tx*8;
        *(float4*)&AO[row]     = w0;
        *(float4*)&AO[row + 4] = w1;
    }
}

// ---------------------------------------------------------------------------
extern "C" void kernel_launch(void* const* d_in, const int* in_sizes, int n_in,
                              void* d_out, int out_size) {
    const float*     hidden = (const float*)d_in[0];
    const float*     q_w    = (const float*)d_in[2];
    const float*     kv_a_w = (const float*)d_in[3];
    const float*     ln_w   = (const float*)d_in[4];
    const float*     kv_b_w = (const float*)d_in[5];
    const float*     o_w    = (const float*)d_in[6];
    float*           out    = (float*)d_out;

    float *pQ, *pCKV, *pCLN, *pKV, *pKPE, *pAO;
    cudaGetSymbolAddress((void**)&pQ,   g_Q);
    cudaGetSymbolAddress((void**)&pCKV, g_CKV);
    cudaGetSymbolAddress((void**)&pCLN, g_CLN);
    cudaGetSymbolAddress((void**)&pKV,  g_KV);
    cudaGetSymbolAddress((void**)&pKPE, g_KPE);
    cudaGetSymbolAddress((void**)&pAO,  g_AO);

    cudaFuncSetAttribute(attn_kernel, cudaFuncAttributeMaxDynamicSharedMemorySize,
                         (int)ATTN_SMEM);

    dim3 blk(256);
    // 1. Q projection: [4096,2048] x [3072,2048]^T
    gemm_nt<<<dim3(NQ_/64, M_/64), blk>>>(hidden, q_w, pQ, M_, NQ_, HID_);
    // 2. KV-A projection: [4096,2048] x [576,2048]^T
    gemm_nt<<<dim3(CKVW_/64, M_/64), blk>>>(hidden, kv_a_w, pCKV, M_, CKVW_, HID_);
    // 3. RMSNorm on c
    rmsnorm_k<<<M_, 128>>>(pCKV, ln_w, pCLN);
    // 4. KV-B projection: [4096,512] x [4096,512]^T
    gemm_nt<<<dim3(NKV_/64, M_/64), blk>>>(pCLN, kv_b_w, pKV, M_, NKV_, RANK_);
    // 5/6. RoPE
    rope_q<<<(M_*NH_)/8, 256>>>(pQ);      // 8 warps/block, one (m,h) per warp
    rope_k<<<M_/8, 256>>>(pCKV, pKPE);
    // 7. Attention
    attn_kernel<<<dim3(S_/64, NH_, B_), blk, ATTN_SMEM>>>(pQ, pKV, pKPE, pAO);
    // 8. Output projection -> d_out
    gemm_nt<<<dim3(HID_/64, M_/64), blk>>>(pAO, o_w, out, M_, HID_, HID_);
}

// round 4
// speedup vs baseline: 1.8002x; 1.7971x over previous
#include <cuda_runtime.h>
#include <math.h>

// Problem constants
#define B_     2
#define S_     2048
#define HID_   2048
#define NH_    16
#define DQ_    192
#define DNOPE_ 128
#define DROPE_ 64
#define DV_    128
#define RANK_  512
#define M_     (B_*S_)            // 4096
#define NQ_    (NH_*DQ_)          // 3072
#define NKV_   (NH_*(DNOPE_+DV_)) // 4096
#define CKVW_  (RANK_+DROPE_)     // 576

// Scratch (device globals; no runtime allocation allowed)
__device__ float g_Q  [M_*NQ_];
__device__ float g_CKV[M_*CKVW_];
__device__ float g_CLN[M_*RANK_];
__device__ float g_KV [M_*NKV_];
__device__ float g_KPE[M_*DROPE_];
__device__ float g_AO [M_*NH_*DV_];

// ---------------------------------------------------------------------------
// tf32 mma helpers. Fragment layouts (m16n8k8.row.col):
//  A: a0=(r=L>>2, k=L&3)  a1=(r+8,k)  a2=(r,k+4)  a3=(r+8,k+4)
//  B: b0=(k=L&3, n=L>>2)  b1=(k+4, n)
//  C: c0=(r=L>>2, c=2(L&3)) c1=(r,c+1) c2=(r+8,c) c3=(r+8,c+1)
// Smem is pre-packed so an A fragment is one LDS.128 and B one LDS.64.
//  A pack: idx = ((mt*KSN+ks)*32 + lane)*4 + j
//  B pack: idx = ((nt*KSN+ks)*32 + lane)*2 + j
// ---------------------------------------------------------------------------
__device__ __forceinline__ unsigned f2tf(float x) {
    unsigned u; asm("cvt.rna.tf32.f32 %0, %1;" : "=r"(u) : "f"(x)); return u;
}
__device__ __forceinline__ void mma8(float* c, const unsigned* a, unsigned b0, unsigned b1) {
    asm volatile("mma.sync.aligned.m16n8k8.row.col.f32.tf32.tf32.f32 "
                 "{%0,%1,%2,%3},{%4,%5,%6,%7},{%8,%9},{%0,%1,%2,%3};"
                 : "+f"(c[0]), "+f"(c[1]), "+f"(c[2]), "+f"(c[3])
                 : "r"(a[0]), "r"(a[1]), "r"(a[2]), "r"(a[3]), "r"(b0), "r"(b1));
}
// pack float4 spanning 4 consecutive k (c%4==0) into A layout
__device__ __forceinline__ void packA(unsigned* S, int KSN, int r, int c, float4 v) {
    int mt = r >> 4, rr = r & 15;
    unsigned* p = S + (((mt*KSN + (c>>3))*32 + (rr&7)*4) << 2) + ((rr>>3) + (((c>>2)&1) << 1));
    p[0] = f2tf(v.x); p[4] = f2tf(v.y); p[8] = f2tf(v.z); p[12] = f2tf(v.w);
}
// pack one scalar into A layout
__device__ __forceinline__ void packAs(unsigned* S, int KSN, int r, int c, float v) {
    int mt = r >> 4, rr = r & 15, cc = c & 7;
    S[((mt*KSN + (c>>3))*32 + (rr&7)*4 + (cc&3))*4 + (rr>>3) + ((cc>>2) << 1)] = f2tf(v);
}
// pack float4 spanning 4 consecutive k (c%4==0) into B layout
__device__ __forceinline__ void packB(unsigned* S, int KSN, int n, int c, float4 v) {
    int nt = n >> 3, nn = n & 7;
    unsigned* p = S + (((nt*KSN + (c>>3))*32 + nn*4) << 1) + ((c>>2)&1);
    p[0] = f2tf(v.x); p[2] = f2tf(v.y); p[4] = f2tf(v.z); p[6] = f2tf(v.w);
}
// pack float4 spanning 4 consecutive n (n%4==0), fixed k, into B layout
__device__ __forceinline__ void packBn4(unsigned* S, int KSN, int n, int k, float4 v) {
    int nt = n >> 3, nn = n & 7, ks = k >> 3, cc = k & 7;
    unsigned* p = S + (((nt*KSN + ks)*32 + nn*4 + (cc&3)) << 1) + (cc>>2);
    p[0] = f2tf(v.x); p[8] = f2tf(v.y); p[16] = f2tf(v.z); p[24] = f2tf(v.w);
}

// ---------------------------------------------------------------------------
// tf32 NT GEMM: C[M][N] = A[M][K] * W[N][K]^T. 128x128x16 tiles, 8 warps,
// warp tile 32x64 (2 m16 x 8 n8), double-buffered packed smem.
// ---------------------------------------------------------------------------
__global__ __launch_bounds__(256, 2)
void gemm_tf32(const float* __restrict__ A, const float* __restrict__ W,
               float* __restrict__ C, int M, int N, int K) {
    __shared__ unsigned As[2][2048];   // 8 mtiles * 2 ks * 32 lanes * 4
    __shared__ unsigned Bs[2][2048];   // 16 ntiles * 2 ks * 32 lanes * 2
    int tid = threadIdx.x, lane = tid & 31, warp = tid >> 5;
    int wm = warp >> 1, wn = warp & 1;
    int m0 = blockIdx.y * 128, n0 = blockIdx.x * 128;
    int ra = tid >> 2, ca = (tid & 3) * 4;

    const float* Ap  = A + (size_t)(m0 + ra) * K + ca;
    const float* Ap2 = Ap + (size_t)64 * K;
    int rn1 = n0 + ra;      if (rn1 > N - 1) rn1 = N - 1;
    int rn2 = n0 + ra + 64; if (rn2 > N - 1) rn2 = N - 1;
    const float* Wp  = W + (size_t)rn1 * K + ca;
    const float* Wp2 = W + (size_t)rn2 * K + ca;

    float acc[2][8][4];
    #pragma unroll
    for (int i = 0; i < 2; i++)
        #pragma unroll
        for (int j = 0; j < 8; j++)
            #pragma unroll
            for (int k = 0; k < 4; k++) acc[i][j][k] = 0.0f;

    float4 av0 = *(const float4*)Ap,  av1 = *(const float4*)Ap2;
    float4 bv0 = *(const float4*)Wp,  bv1 = *(const float4*)Wp2;
    packA(As[0], 2, ra, ca, av0); packA(As[0], 2, ra + 64, ca, av1);
    packB(Bs[0], 2, ra, ca, bv0); packB(Bs[0], 2, ra + 64, ca, bv1);
    __syncthreads();

    int nb = K >> 4;
    for (int it = 0; it < nb; it++) {
        int cur = it & 1;
        if (it + 1 < nb) {
            int off = (it + 1) << 4;
            av0 = *(const float4*)(Ap + off);  av1 = *(const float4*)(Ap2 + off);
            bv0 = *(const float4*)(Wp + off);  bv1 = *(const float4*)(Wp2 + off);
        }
        const unsigned* a_s = As[cur];
        const unsigned* b_s = Bs[cur];
        #pragma unroll
        for (int ks = 0; ks < 2; ks++) {
            uint4 af0 = *(const uint4*)(a_s + (((wm*2 + 0)*2 + ks)*32 + lane)*4);
            uint4 af1 = *(const uint4*)(a_s + (((wm*2 + 1)*2 + ks)*32 + lane)*4);
            #pragma unroll
            for (int nt = 0; nt < 8; nt++) {
                uint2 bf = *(const uint2*)(b_s + (((wn*8 + nt)*2 + ks)*32 + lane)*2);
                mma8(acc[0][nt], (const unsigned*)&af0, bf.x, bf.y);
                mma8(acc[1][nt], (const unsigned*)&af1, bf.x, bf.y);
            }
        }
        if (it + 1 < nb) {
            __syncthreads();
            unsigned* An = As[cur ^ 1]; unsigned* Bn = Bs[cur ^ 1];
            packA(An, 2, ra, ca, av0); packA(An, 2, ra + 64, ca, av1);
            packB(Bn, 2, ra, ca, bv0); packB(Bn, 2, ra + 64, ca, bv1);
            __syncthreads();
        }
    }
    #pragma unroll
    for (int mt = 0; mt < 2; mt++) {
        int r0 = m0 + wm*32 + mt*16 + (lane >> 2);
        #pragma unroll
        for (int nt = 0; nt < 8; nt++) {
            int cb = n0 + wn*64 + nt*8 + (lane & 3)*2;
            if (cb < N) {
                *(float2*)&C[(size_t)r0 * N + cb]       = make_float2(acc[mt][nt][0], acc[mt][nt][1]);
                *(float2*)&C[(size_t)(r0 + 8) * N + cb] = make_float2(acc[mt][nt][2], acc[mt][nt][3]);
            }
        }
    }
}

// ---------------------------------------------------------------------------
// RMSNorm over first 512 of each 576-wide CKV row, times gamma.
// ---------------------------------------------------------------------------
__global__ void rmsnorm_k(const float* __restrict__ ckv, const float* __restrict__ w,
                          float* __restrict__ out) {
    int m = blockIdx.x;
    int tid = threadIdx.x;   // 128 threads
    const float* row = ckv + (size_t)m * CKVW_;
    float4 v = *(const float4*)(row + tid * 4);
    float ss = v.x*v.x + v.y*v.y + v.z*v.z + v.w*v.w;
    #pragma unroll
    for (int o = 16; o; o >>= 1) ss += __shfl_xor_sync(0xffffffffu, ss, o);
    __shared__ float sacc[4];
    if ((tid & 31) == 0) sacc[tid >> 5] = ss;
    __syncthreads();
    float tot = sacc[0] + sacc[1] + sacc[2] + sacc[3];
    float inv = rsqrtf(tot * (1.0f/512.0f) + 1e-6f);
    float4 wv = *(const float4*)(w + tid * 4);
    float4 o4 = make_float4(v.x*inv*wv.x, v.y*inv*wv.y, v.z*inv*wv.z, v.w*inv*wv.w);
    *(float4*)(out + (size_t)m * RANK_ + tid * 4) = o4;
}

// ---------------------------------------------------------------------------
// YaRN rope (low=10, high=23, mscale ratio = 1). Position = m % S_.
// ---------------------------------------------------------------------------
__device__ __forceinline__ float yarn_inv_freq(int j) {
    float fe = powf(10000.0f, -(float)(2*j) / 64.0f);
    float fi = fe * (1.0f / 40.0f);
    float ramp = fminf(fmaxf(((float)j - 10.0f) * (1.0f/13.0f), 0.0f), 1.0f);
    return fi * ramp + fe * (1.0f - ramp);
}

__global__ void rope_q(float* __restrict__ Q) {
    int warp = (blockIdx.x * blockDim.x + threadIdx.x) >> 5;
    int lane = threadIdx.x & 31;
    int m = warp >> 4, h = warp & 15;
    float* p = Q + (size_t)m * NQ_ + h * DQ_ + DNOPE_;
    float x0 = p[2*lane], x1 = p[2*lane+1];
    float ang = (float)(m % S_) * yarn_inv_freq(lane);
    float s, c;
    sincosf(ang, &s, &c);
    float y0 = x0*c - x1*s;
    float y1 = x1*c + x0*s;
    __syncwarp();
    p[lane]      = y0;
    p[lane + 32] = y1;
}

__global__ void rope_k(const float* __restrict__ ckv, float* __restrict__ kpe) {
    int warp = (blockIdx.x * blockDim.x + threadIdx.x) >> 5;
    int lane = threadIdx.x & 31;
    const float* p = ckv + (size_t)warp * CKVW_ + RANK_;
    float x0 = p[2*lane], x1 = p[2*lane+1];
    float ang = (float)(warp % S_) * yarn_inv_freq(lane);
    float s, c;
    sincosf(ang, &s, &c);
    kpe[(size_t)warp * DROPE_ + lane]      = x0*c - x1*s;
    kpe[(size_t)warp * DROPE_ + lane + 32] = x1*c + x0*s;
}

// ---------------------------------------------------------------------------
// Flash attention with tf32 mma. Block = (b, h, 64-q tile), 256 threads.
// Score warp tile m16 x n32 (wm=warp>>1, wn=warp&1); PV warp tile m16 x n64.
// Smem (unsigned words):
//   Qs  A-pack 64x192 (KSN=24) : 12288
//   Ks  B-pack 64x192 (KSN=24) : 12288
//   Vs  B-pack n=128,k=64(KSN=8): 8192
//   Ps  A-pack 64x64  (KSN=8)  : 4096
//   rmax/rsum floats 2x64 each  : 256
// ---------------------------------------------------------------------------
#define ATTN_SMEM_W (12288 + 12288 + 8192 + 4096 + 256)
#define ATTN_SMEM   (ATTN_SMEM_W * 4)

__global__ __launch_bounds__(256, 1)
void attn_tf32(const float* __restrict__ Q, const float* __restrict__ KV,
               const float* __restrict__ KPE, float* __restrict__ AO) {
    extern __shared__ unsigned smu[];
    unsigned* Qs = smu;
    unsigned* Ks = smu + 12288;
    unsigned* Vs = smu + 24576;
    unsigned* Ps = smu + 32768;
    float* rmax = (float*)(smu + 36864);   // [2][64]
    float* rsum = (float*)(smu + 36992);   // [2][64]

    int tid = threadIdx.x, lane = tid & 31, warp = tid >> 5;
    int wm = warp >> 1, wn = warp & 1;
    int qt = gridDim.x - 1 - blockIdx.x;
    int h = blockIdx.y, b = blockIdx.z;
    int q0 = qt * 64;
    const size_t base = (size_t)b * S_;

    // Q tile -> packed A layout (resident across k-tiles)
    for (int idx = tid; idx < 64*48; idx += 256) {
        int r = idx / 48, c4 = idx % 48;
        float4 v = *(const float4*)(Q + (base + q0 + r) * NQ_ + h * DQ_ + c4*4);
        packA(Qs, 24, r, c4*4, v);
    }

    float m_r[2] = {-INFINITY, -INFINITY};
    float l_r[2] = {0.0f, 0.0f};
    float o[8][4];
    #pragma unroll
    for (int nt = 0; nt < 8; nt++)
        #pragma unroll
        for (int j = 0; j < 4; j++) o[nt][j] = 0.0f;

    const float scale = 0.072168783648703f;   // 1/sqrt(192)
    int row0 = wm*16 + (lane >> 2);
    int row1 = row0 + 8;

    for (int kt = 0; kt <= qt; kt++) {
        int k0 = kt * 64;
        __syncthreads();   // prev PV done (and Qs ready on first iter)
        // K tile: d<128 from KV k_nope, d>=128 from rotated KPE
        for (int idx = tid; idx < 64*48; idx += 256) {
            int r = idx / 48, c4 = idx % 48;
            float4 v;
            if (c4 < 32)
                v = *(const float4*)(KV + (base + k0 + r) * NKV_ + h*256 + c4*4);
            else
                v = *(const float4*)(KPE + (base + k0 + r) * DROPE_ + (c4 - 32)*4);
            packB(Ks, 24, r, c4*4, v);
        }
        // V tile (transpose at pack: B operand n=d, k=kpos)
        for (int idx = tid; idx < 64*32; idx += 256) {
            int r = idx / 32, d4 = idx % 32;
            float4 v = *(const float4*)(KV + (base + k0 + r) * NKV_ + h*256 + 128 + d4*4);
            packBn4(Vs, 8, d4*4, r, v);
        }
        __syncthreads();

        // S = Q K^T
        float sacc[4][4];
        #pragma unroll
        for (int nt = 0; nt < 4; nt++)
            #pragma unroll
            for (int j = 0; j < 4; j++) sacc[nt][j] = 0.0f;
        #pragma unroll 4
        for (int ks = 0; ks < 24; ks++) {
            uint4 af = *(const uint4*)(Qs + ((wm*24 + ks)*32 + lane)*4);
            #pragma unroll
            for (int nt = 0; nt < 4; nt++) {
                uint2 bf = *(const uint2*)(Ks + (((wn*4 + nt)*24 + ks)*32 + lane)*2);
                mma8(sacc[nt], (const unsigned*)&af, bf.x, bf.y);
            }
        }
        // scale + causal mask (only diagonal tile can mask)
        bool diag = (kt == qt);
        #pragma unroll
        for (int nt = 0; nt < 4; nt++) {
            int cb = k0 + wn*32 + nt*8 + (lane & 3)*2;
            #pragma unroll
            for (int j = 0; j < 4; j++) {
                float v = sacc[nt][j] * scale;
                if (diag) {
                    int col = cb + (j & 1);
                    int row = q0 + ((j < 2) ? row0 : row1);
                    if (col > row) v = -1e30f;
                }
                sacc[nt][j] = v;
            }
        }
        // row max (4-lane shfl + cross-warp via smem)
        float mx0 = fmaxf(fmaxf(sacc[0][0], sacc[0][1]), fmaxf(sacc[1][0], sacc[1][1]));
        mx0 = fmaxf(mx0, fmaxf(fmaxf(sacc[2][0], sacc[2][1]), fmaxf(sacc[3][0], sacc[3][1])));
        float mx1 = fmaxf(fmaxf(sacc[0][2], sacc[0][3]), fmaxf(sacc[1][2], sacc[1][3]));
        mx1 = fmaxf(mx1, fmaxf(fmaxf(sacc[2][2], sacc[2][3]), fmaxf(sacc[3][2], sacc[3][3])));
        mx0 = fmaxf(mx0, __shfl_xor_sync(0xffffffffu, mx0, 1));
        mx0 = fmaxf(mx0, __shfl_xor_sync(0xffffffffu, mx0, 2));
        mx1 = fmaxf(mx1, __shfl_xor_sync(0xffffffffu, mx1, 1));
        mx1 = fmaxf(mx1, __shfl_xor_sync(0xffffffffu, mx1, 2));
        if ((lane & 3) == 0) { rmax[wn*64 + row0] = mx0; rmax[wn*64 + row1] = mx1; }
        __syncthreads();
        float nm0 = fmaxf(m_r[0], fmaxf(rmax[row0], rmax[64 + row0]));
        float nm1 = fmaxf(m_r[1], fmaxf(rmax[row1], rmax[64 + row1]));
        float corr0 = __expf(m_r[0] - nm0), corr1 = __expf(m_r[1] - nm1);
        m_r[0] = nm0; m_r[1] = nm1;

        float rs0 = 0.0f, rs1 = 0.0f;
        #pragma unroll
        for (int nt = 0; nt < 4; nt++) {
            int cbl = wn*32 + nt*8 + (lane & 3)*2;
            float p0 = __expf(sacc[nt][0] - nm0), p1 = __expf(sacc[nt][1] - nm0);
            float p2 = __expf(sacc[nt][2] - nm1), p3 = __expf(sacc[nt][3] - nm1);
            rs0 += p0 + p1; rs1 += p2 + p3;
            packAs(Ps, 8, row0, cbl,     p0);
            packAs(Ps, 8, row0, cbl + 1, p1);
            packAs(Ps, 8, row1, cbl,     p2);
            packAs(Ps, 8, row1, cbl + 1, p3);
        }
        rs0 += __shfl_xor_sync(0xffffffffu, rs0, 1);
        rs0 += __shfl_xor_sync(0xffffffffu, rs0, 2);
        rs1 += __shfl_xor_sync(0xffffffffu, rs1, 1);
        rs1 += __shfl_xor_sync(0xffffffffu, rs1, 2);
        if ((lane & 3) == 0) { rsum[wn*64 + row0] = rs0; rsum[wn*64 + row1] = rs1; }
        __syncthreads();
        l_r[0] = l_r[0] * corr0 + rsum[row0] + rsum[64 + row0];
        l_r[1] = l_r[1] * corr1 + rsum[row1] + rsum[64 + row1];

        // O = O*corr + P V
        #pragma unroll
        for (int nt = 0; nt < 8; nt++) {
            o[nt][0] *= corr0; o[nt][1] *= corr0;
            o[nt][2] *= corr1; o[nt][3] *= corr1;
        }
        #pragma unroll
        for (int ks = 0; ks < 8; ks++) {
            uint4 af = *(const uint4*)(Ps + ((wm*8 + ks)*32 + lane)*4);
            #pragma unroll
            for (int nt = 0; nt < 8; nt++) {
                uint2 bf = *(const uint2*)(Vs + (((wn*8 + nt)*8 + ks)*32 + lane)*2);
                mma8(o[nt], (const unsigned*)&af, bf.x, bf.y);
            }
        }
    }

    // epilogue
    float inv0 = 1.0f / l_r[0], inv1 = 1.0f / l_r[1];
    #pragma unroll
    for (int nt = 0; nt < 8; nt++) {
        int d = wn*64 + nt*8 + (lane & 3)*2;
        size_t r0 = (base + q0 + row0) * (size_t)(NH_*DV_) + h*DV_ + d;
        size_t r1 = (base + q0 + row1) * (size_t)(NH_*DV_) + h*DV_ + d;
        *(float2*)&AO[r0] = make_float2(o[nt][0]*inv0, o[nt][1]*inv0);
        *(float2*)&AO[r1] = make_float2(o[nt][2]*inv1, o[nt][3]*inv1);
    }
}

// ---------------------------------------------------------------------------
extern "C" void kernel_launch(void* const* d_in, const int* in_sizes, int n_in,
                              void* d_out, int out_size) {
    const float* hidden = (const float*)d_in[0];
    const float* q_w    = (const float*)d_in[2];
    const float* kv_a_w = (const float*)d_in[3];
    const float* ln_w   = (const float*)d_in[4];
    const float* kv_b_w = (const float*)d_in[5];
    const float* o_w    = (const float*)d_in[6];
    float*       out    = (float*)d_out;

    float *pQ, *pCKV, *pCLN, *pKV, *pKPE, *pAO;
    cudaGetSymbolAddress((void**)&pQ,   g_Q);
    cudaGetSymbolAddress((void**)&pCKV, g_CKV);
    cudaGetSymbolAddress((void**)&pCLN, g_CLN);
    cudaGetSymbolAddress((void**)&pKV,  g_KV);
    cudaGetSymbolAddress((void**)&pKPE, g_KPE);
    cudaGetSymbolAddress((void**)&pAO,  g_AO);

    cudaFuncSetAttribute(attn_tf32, cudaFuncAttributeMaxDynamicSharedMemorySize,
                         (int)ATTN_SMEM);

    dim3 blk(256);
    // 1. Q projection: [4096,2048] x [3072,2048]^T
    gemm_tf32<<<dim3(NQ_/128, M_/128), blk>>>(hidden, q_w, pQ, M_, NQ_, HID_);
    // 2. KV-A projection: [4096,2048] x [576,2048]^T  (N=576 -> 5 n-blocks)
    gemm_tf32<<<dim3((CKVW_+127)/128, M_/128), blk>>>(hidden, kv_a_w, pCKV, M_, CKVW_, HID_);
    // 3. RMSNorm on c
    rmsnorm_k<<<M_, 128>>>(pCKV, ln_w, pCLN);
    // 4. KV-B projection: [4096,512] x [4096,512]^T
    gemm_tf32<<<dim3(NKV_/128, M_/128), blk>>>(pCLN, kv_b_w, pKV, M_, NKV_, RANK_);
    // 5/6. RoPE
    rope_q<<<(M_*NH_)/8, 256>>>(pQ);
    rope_k<<<M_/8, 256>>>(pCKV, pKPE);
    // 7. Attention
    attn_tf32<<<dim3(S_/64, NH_, B_), blk, ATTN_SMEM>>>(pQ, pKV, pKPE, pAO);
    // 8. Output projection -> d_out
    gemm_tf32<<<dim3(HID_/128, M_/128), blk>>>(pAO, o_w, out, M_, HID_, HID_);
}

// round 6
// speedup vs baseline: 5.5871x; 3.1036x over previous
#include <cuda_runtime.h>
#include <cuda_fp16.h>
#include <math.h>
#include <stdint.h>

// Problem constants
#define B_     2
#define S_     2048
#define HID_   2048
#define NH_    16
#define DQ_    192
#define DNOPE_ 128
#define DROPE_ 64
#define DV_    128
#define RANK_  512
#define M_     (B_*S_)            // 4096
#define NQ_    (NH_*DQ_)          // 3072
#define NKV_   (NH_*(DNOPE_+DV_)) // 4096
#define CKVW_  (RANK_+DROPE_)     // 576

// Scratch (device globals; no runtime allocation allowed)
__device__ float g_Q  [M_*NQ_];
__device__ float g_CKV[M_*CKVW_];
__device__ float g_CLN[M_*RANK_];
__device__ float g_KV [M_*NKV_];
__device__ float g_KPE[M_*DROPE_];
__device__ float g_AO [M_*NH_*DV_];

// ---------------------------------------------------------------------------
// Helpers
// ---------------------------------------------------------------------------
__device__ __forceinline__ uint32_t smem_u32(const void* p) {
    uint32_t a;
    asm("{ .reg .u64 t; cvta.to.shared.u64 t, %1; cvt.u32.u64 %0, t; }" : "=r"(a) : "l"(p));
    return a;
}
__device__ __forceinline__ unsigned h2u(float a, float b) {
    __half2 h = __floats2half2_rn(a, b);
    return *(unsigned*)&h;
}
// fp16 mma m16n8k16, fp32 accumulate
#define MMA16(C, A, B0, B1) \
    asm volatile("mma.sync.aligned.m16n8k16.row.col.f32.f16.f16.f32 " \
        "{%0,%1,%2,%3},{%4,%5,%6,%7},{%8,%9},{%0,%1,%2,%3};" \
        : "+f"((C)[0]), "+f"((C)[1]), "+f"((C)[2]), "+f"((C)[3]) \
        : "r"((A)[0]), "r"((A)[1]), "r"((A)[2]), "r"((A)[3]), "r"(B0), "r"(B1))

#define LDSM4(R, addr) \
    asm volatile("ldmatrix.sync.aligned.m8n8.x4.shared.b16 {%0,%1,%2,%3}, [%4];" \
        : "=r"((R)[0]), "=r"((R)[1]), "=r"((R)[2]), "=r"((R)[3]) : "r"(addr))
#define LDSM4T(R, addr) \
    asm volatile("ldmatrix.sync.aligned.m8n8.x4.trans.shared.b16 {%0,%1,%2,%3}, [%4];" \
        : "=r"((R)[0]), "=r"((R)[1]), "=r"((R)[2]), "=r"((R)[3]) : "r"(addr))

#define STS128(addr, v) \
    asm volatile("st.shared.v4.b32 [%0], {%1,%2,%3,%4};" \
        :: "r"(addr), "r"((v).x), "r"((v).y), "r"((v).z), "r"((v).w) : "memory")
#define STS32(addr, v) \
    asm volatile("st.shared.b32 [%0], %1;" :: "r"(addr), "r"(v) : "memory")

// Swizzled smem offsets (half tiles, 16B chunks)
// 64B rows (GEMM, BK=32 halves): chunk c in 0..3
__device__ __forceinline__ uint32_t off64(uint32_t row, uint32_t c) {
    return row * 64u + (((c ^ (row >> 1)) & 3u) << 4);
}
// rs-byte rows (rs multiple of 128): chunk c
__device__ __forceinline__ uint32_t offN(uint32_t row, uint32_t rs, uint32_t c) {
    return row * rs + ((c >> 3) << 7) + (((c ^ row) & 7u) << 4);
}

// ---------------------------------------------------------------------------
// fp16 NT GEMM: C[M][N](fp32) = A[M][K] * W[N][K]^T  (fp32 in, fp16 mma)
// Tile 128x128x32, 256 threads, warps 4x2 (warp tile 32x64).
// Single __syncthreads per k-slab; register prefetch double buffer.
// ---------------------------------------------------------------------------
__global__ __launch_bounds__(256, 2)
void gemm_fp16(const float* __restrict__ A, const float* __restrict__ W,
               float* __restrict__ C, int M, int N, int K) {
    __shared__ __align__(16) uint8_t smraw[2 * 16384];   // stage: A 8KB | B 8KB
    uint32_t sb = smem_u32(smraw);
    int tid = threadIdx.x, lane = tid & 31, warp = tid >> 5;
    int wm = warp >> 1, wn = warp & 1;
    int m0 = blockIdx.y * 128, n0 = blockIdx.x * 128;

    // producer job indices: 512 A-chunks + 512 B-chunks, 2 each per thread
    int rowJ[2], colJ[2];
    #pragma unroll
    for (int i = 0; i < 2; i++) { int idx = tid + i * 256; rowJ[i] = idx >> 2; colJ[i] = idx & 3; }
    int rnJ[2];
    #pragma unroll
    for (int i = 0; i < 2; i++) { int r = n0 + rowJ[i]; rnJ[i] = (r > N - 1) ? (N - 1) : r; }

    float acc[2][8][4];
    #pragma unroll
    for (int a = 0; a < 2; a++)
        #pragma unroll
        for (int b = 0; b < 8; b++)
            #pragma unroll
            for (int c = 0; c < 4; c++) acc[a][b][c] = 0.0f;

    float4 fa[2][2], fb[2][2];
    auto load_regs = [&](int s) {
        int kof = s * 32;
        #pragma unroll
        for (int i = 0; i < 2; i++) {
            const float* p = A + (size_t)(m0 + rowJ[i]) * K + kof + colJ[i] * 8;
            fa[i][0] = *(const float4*)p;
            fa[i][1] = *(const float4*)(p + 4);
            const float* q = W + (size_t)rnJ[i] * K + kof + colJ[i] * 8;
            fb[i][0] = *(const float4*)q;
            fb[i][1] = *(const float4*)(q + 4);
        }
    };
    auto store_stage = [&](int st) {
        uint32_t ab = sb + st * 16384, bb = ab + 8192;
        #pragma unroll
        for (int i = 0; i < 2; i++) {
            uint4 pk;
            pk.x = h2u(fa[i][0].x, fa[i][0].y); pk.y = h2u(fa[i][0].z, fa[i][0].w);
            pk.z = h2u(fa[i][1].x, fa[i][1].y); pk.w = h2u(fa[i][1].z, fa[i][1].w);
            STS128(ab + off64(rowJ[i], colJ[i]), pk);
            pk.x = h2u(fb[i][0].x, fb[i][0].y); pk.y = h2u(fb[i][0].z, fb[i][0].w);
            pk.z = h2u(fb[i][1].x, fb[i][1].y); pk.w = h2u(fb[i][1].z, fb[i][1].w);
            STS128(bb + off64(rowJ[i], colJ[i]), pk);
        }
    };

    load_regs(0);
    store_stage(0);
    __syncthreads();

    int ns = K >> 5;
    for (int s = 0; s < ns; s++) {
        int st = s & 1;
        if (s + 1 < ns) load_regs(s + 1);
        uint32_t ab = sb + st * 16384, bb = ab + 8192;
        #pragma unroll
        for (int ks = 0; ks < 2; ks++) {
            unsigned af[2][4];
            #pragma unroll
            for (int mt = 0; mt < 2; mt++) {
                uint32_t row = wm * 32 + mt * 16 + (lane & 15);
                uint32_t c = ks * 2 + (lane >> 4);
                LDSM4(af[mt], ab + off64(row, c));
            }
            #pragma unroll
            for (int nb = 0; nb < 4; nb++) {
                unsigned bf[4];
                uint32_t rowb = wn * 64 + nb * 16 + (lane & 7) + ((lane >> 4) << 3);
                uint32_t cb = ks * 2 + ((lane >> 3) & 1);
                LDSM4(bf, bb + off64(rowb, cb));
                MMA16(acc[0][nb*2],   af[0], bf[0], bf[1]);
                MMA16(acc[0][nb*2+1], af[0], bf[2], bf[3]);
                MMA16(acc[1][nb*2],   af[1], bf[0], bf[1]);
                MMA16(acc[1][nb*2+1], af[1], bf[2], bf[3]);
            }
        }
        if (s + 1 < ns) store_stage(st ^ 1);
        __syncthreads();
    }

    #pragma unroll
    for (int mt = 0; mt < 2; mt++) {
        int r0 = m0 + wm * 32 + mt * 16 + (lane >> 2);
        #pragma unroll
        for (int nt = 0; nt < 8; nt++) {
            int cb = n0 + wn * 64 + nt * 8 + (lane & 3) * 2;
            if (cb < N) {
                *(float2*)&C[(size_t)r0 * N + cb]       = make_float2(acc[mt][nt][0], acc[mt][nt][1]);
                *(float2*)&C[(size_t)(r0 + 8) * N + cb] = make_float2(acc[mt][nt][2], acc[mt][nt][3]);
            }
        }
    }
}

// ---------------------------------------------------------------------------
// RMSNorm over first 512 of each 576-wide CKV row, times gamma.
// ---------------------------------------------------------------------------
__global__ void rmsnorm_k(const float* __restrict__ ckv, const float* __restrict__ w,
                          float* __restrict__ out) {
    int m = blockIdx.x;
    int tid = threadIdx.x;   // 128 threads
    const float* row = ckv + (size_t)m * CKVW_;
    float4 v = *(const float4*)(row + tid * 4);
    float ss = v.x*v.x + v.y*v.y + v.z*v.z + v.w*v.w;
    #pragma unroll
    for (int o = 16; o; o >>= 1) ss += __shfl_xor_sync(0xffffffffu, ss, o);
    __shared__ float sacc[4];
    if ((tid & 31) == 0) sacc[tid >> 5] = ss;
    __syncthreads();
    float tot = sacc[0] + sacc[1] + sacc[2] + sacc[3];
    float inv = rsqrtf(tot * (1.0f/512.0f) + 1e-6f);
    float4 wv = *(const float4*)(w + tid * 4);
    float4 o4 = make_float4(v.x*inv*wv.x, v.y*inv*wv.y, v.z*inv*wv.z, v.w*inv*wv.w);
    *(float4*)(out + (size_t)m * RANK_ + tid * 4) = o4;
}

// ---------------------------------------------------------------------------
// YaRN rope (low=10, high=23, mscale ratio = 1). Position = m % S_.
// ---------------------------------------------------------------------------
__device__ __forceinline__ float yarn_inv_freq(int j) {
    float fe = powf(10000.0f, -(float)(2*j) / 64.0f);
    float fi = fe * (1.0f / 40.0f);
    float ramp = fminf(fmaxf(((float)j - 10.0f) * (1.0f/13.0f), 0.0f), 1.0f);
    return fi * ramp + fe * (1.0f - ramp);
}

__global__ void rope_q(float* __restrict__ Q) {
    int warp = (blockIdx.x * blockDim.x + threadIdx.x) >> 5;
    int lane = threadIdx.x & 31;
    int m = warp >> 4, h = warp & 15;
    float* p = Q + (size_t)m * NQ_ + h * DQ_ + DNOPE_;
    float x0 = p[2*lane], x1 = p[2*lane+1];
    float ang = (float)(m % S_) * yarn_inv_freq(lane);
    float s, c;
    sincosf(ang, &s, &c);
    float y0 = x0*c - x1*s;
    float y1 = x1*c + x0*s;
    __syncwarp();
    p[lane]      = y0;
    p[lane + 32] = y1;
}

__global__ void rope_k(const float* __restrict__ ckv, float* __restrict__ kpe) {
    int warp = (blockIdx.x * blockDim.x + threadIdx.x) >> 5;
    int lane = threadIdx.x & 31;
    const float* p = ckv + (size_t)warp * CKVW_ + RANK_;
    float x0 = p[2*lane], x1 = p[2*lane+1];
    float ang = (float)(warp % S_) * yarn_inv_freq(lane);
    float s, c;
    sincosf(ang, &s, &c);
    kpe[(size_t)warp * DROPE_ + lane]      = x0*c - x1*s;
    kpe[(size_t)warp * DROPE_ + lane + 32] = x1*c + x0*s;
}

// ---------------------------------------------------------------------------
// Flash attention, fp16 mma. Block = (b, h, 64-q tile), 256 threads (8 warps).
// Warp grid 4x2: wm (m16 rows), wn (n32 for scores / n64 for PV).
// Smem halves, byte offsets:
//   Qs [64][192] rs=384 @ 0      (24576)
//   Ks [64][192] rs=384 @ 24576  (24576)
//   Vs [64][128] rs=256 @ 49152  (16384)
//   Ps [64][64]  rs=128 @ 65536  (8192)
//   rmax [2][64] f32 @ 73728, rsum @ 74240. Total 74752 B -> 2 CTAs/SM.
// ---------------------------------------------------------------------------
#define AT_QS 0
#define AT_KS 24576
#define AT_VS 49152
#define AT_PS 65536
#define AT_RED 73728
#define ATTN_SMEM (74752)

__global__ __launch_bounds__(256, 2)
void attn_fp16(const float* __restrict__ Q, const float* __restrict__ KV,
               const float* __restrict__ KPE, float* __restrict__ AO) {
    extern __shared__ __align__(16) uint8_t smraw[];
    uint32_t sb = smem_u32(smraw);
    float* rmax = (float*)(smraw + AT_RED);         // [2][64]
    float* rsum = (float*)(smraw + AT_RED + 512);   // [2][64]

    int tid = threadIdx.x, lane = tid & 31, warp = tid >> 5;
    int wm = warp >> 1, wn = warp & 1;
    int qt = gridDim.x - 1 - blockIdx.x;
    int h = blockIdx.y, b = blockIdx.z;
    int q0 = qt * 64;
    const size_t base = (size_t)b * S_;

    // Q tile -> Qs (fp16, swizzled). 1536 chunks, 6 per thread.
    #pragma unroll
    for (int i = 0; i < 6; i++) {
        int idx = tid + i * 256;
        int r = idx / 24, c = idx % 24;
        const float* p = Q + (base + q0 + r) * NQ_ + h * DQ_ + c * 8;
        float4 u = *(const float4*)p, v = *(const float4*)(p + 4);
        uint4 pk;
        pk.x = h2u(u.x, u.y); pk.y = h2u(u.z, u.w);
        pk.z = h2u(v.x, v.y); pk.w = h2u(v.z, v.w);
        STS128(sb + AT_QS + offN(r, 384, c), pk);
    }

    float m_r[2] = {-INFINITY, -INFINITY};
    float l_r[2] = {0.0f, 0.0f};
    float o[8][4];
    #pragma unroll
    for (int nt = 0; nt < 8; nt++)
        #pragma unroll
        for (int j = 0; j < 4; j++) o[nt][j] = 0.0f;

    const float scale = 0.072168783648703f;   // 1/sqrt(192)
    int row0 = wm * 16 + (lane >> 2);
    int row1 = row0 + 8;

    for (int kt = 0; kt <= qt; kt++) {
        int k0 = kt * 64;
        __syncthreads();   // prev PV done; Ks/Vs free (Qs ready first iter)
        // K tile: d<128 from KV k_nope, d>=128 from rotated KPE
        #pragma unroll
        for (int i = 0; i < 6; i++) {
            int idx = tid + i * 256;
            int r = idx / 24, c = idx % 24;
            const float* p;
            if (c < 16) p = KV  + (base + k0 + r) * NKV_ + h * 256 + c * 8;
            else        p = KPE + (base + k0 + r) * DROPE_ + (c - 16) * 8;
            float4 u = *(const float4*)p, v = *(const float4*)(p + 4);
            uint4 pk;
            pk.x = h2u(u.x, u.y); pk.y = h2u(u.z, u.w);
            pk.z = h2u(v.x, v.y); pk.w = h2u(v.z, v.w);
            STS128(sb + AT_KS + offN(r, 384, c), pk);
        }
        // V tile [kpos][d]
        #pragma unroll
        for (int i = 0; i < 4; i++) {
            int idx = tid + i * 256;
            int r = idx / 16, c = idx % 16;
            const float* p = KV + (base + k0 + r) * NKV_ + h * 256 + 128 + c * 8;
            float4 u = *(const float4*)p, v = *(const float4*)(p + 4);
            uint4 pk;
            pk.x = h2u(u.x, u.y); pk.y = h2u(u.z, u.w);
            pk.z = h2u(v.x, v.y); pk.w = h2u(v.z, v.w);
            STS128(sb + AT_VS + offN(r, 256, c), pk);
        }
        __syncthreads();

        // S = Q K^T   (warp: m16 x n32, 12 k16 steps)
        float sacc[4][4];
        #pragma unroll
        for (int nt = 0; nt < 4; nt++)
            #pragma unroll
            for (int j = 0; j < 4; j++) sacc[nt][j] = 0.0f;
        #pragma unroll
        for (int ks = 0; ks < 12; ks++) {
            unsigned qa[4];
            {
                uint32_t row = wm * 16 + (lane & 15);
                uint32_t c = ks * 2 + (lane >> 4);
                LDSM4(qa, sb + AT_QS + offN(row, 384, c));
            }
            #pragma unroll
            for (int nb = 0; nb < 2; nb++) {
                unsigned kb[4];
                uint32_t rowb = wn * 32 + nb * 16 + (lane & 7) + ((lane >> 4) << 3);
                uint32_t cb = ks * 2 + ((lane >> 3) & 1);
                LDSM4(kb, sb + AT_KS + offN(rowb, 384, cb));
                MMA16(sacc[nb*2],   qa, kb[0], kb[1]);
                MMA16(sacc[nb*2+1], qa, kb[2], kb[3]);
            }
        }
        // scale + causal mask (diagonal tile only)
        bool diag = (kt == qt);
        #pragma unroll
        for (int nt = 0; nt < 4; nt++) {
            int cb = k0 + wn * 32 + nt * 8 + (lane & 3) * 2;
            #pragma unroll
            for (int j = 0; j < 4; j++) {
                float v = sacc[nt][j] * scale;
                if (diag) {
                    int col = cb + (j & 1);
                    int row = q0 + ((j < 2) ? row0 : row1);
                    if (col > row) v = -1e30f;
                }
                sacc[nt][j] = v;
            }
        }
        // online softmax
        float mx0 = fmaxf(fmaxf(sacc[0][0], sacc[0][1]), fmaxf(sacc[1][0], sacc[1][1]));
        mx0 = fmaxf(mx0, fmaxf(fmaxf(sacc[2][0], sacc[2][1]), fmaxf(sacc[3][0], sacc[3][1])));
        float mx1 = fmaxf(fmaxf(sacc[0][2], sacc[0][3]), fmaxf(sacc[1][2], sacc[1][3]));
        mx1 = fmaxf(mx1, fmaxf(fmaxf(sacc[2][2], sacc[2][3]), fmaxf(sacc[3][2], sacc[3][3])));
        mx0 = fmaxf(mx0, __shfl_xor_sync(0xffffffffu, mx0, 1));
        mx0 = fmaxf(mx0, __shfl_xor_sync(0xffffffffu, mx0, 2));
        mx1 = fmaxf(mx1, __shfl_xor_sync(0xffffffffu, mx1, 1));
        mx1 = fmaxf(mx1, __shfl_xor_sync(0xffffffffu, mx1, 2));
        if ((lane & 3) == 0) { rmax[wn*64 + row0] = mx0; rmax[wn*64 + row1] = mx1; }
        __syncthreads();
        float nm0 = fmaxf(m_r[0], fmaxf(rmax[row0], rmax[64 + row0]));
        float nm1 = fmaxf(m_r[1], fmaxf(rmax[row1], rmax[64 + row1]));
        float corr0 = __expf(m_r[0] - nm0), corr1 = __expf(m_r[1] - nm1);
        m_r[0] = nm0; m_r[1] = nm1;

        float rs0 = 0.0f, rs1 = 0.0f;
        #pragma unroll
        for (int nt = 0; nt < 4; nt++) {
            int cb = wn * 32 + nt * 8 + (lane & 3) * 2;   // local col
            float p0 = __expf(sacc[nt][0] - nm0), p1 = __expf(sacc[nt][1] - nm0);
            float p2 = __expf(sacc[nt][2] - nm1), p3 = __expf(sacc[nt][3] - nm1);
            rs0 += p0 + p1; rs1 += p2 + p3;
            uint32_t a0 = sb + AT_PS + offN(row0, 128, cb >> 3) + (cb & 7) * 2;
            uint32_t a1 = sb + AT_PS + offN(row1, 128, cb >> 3) + (cb & 7) * 2;
            STS32(a0, h2u(p0, p1));
            STS32(a1, h2u(p2, p3));
        }
        rs0 += __shfl_xor_sync(0xffffffffu, rs0, 1);
        rs0 += __shfl_xor_sync(0xffffffffu, rs0, 2);
        rs1 += __shfl_xor_sync(0xffffffffu, rs1, 1);
        rs1 += __shfl_xor_sync(0xffffffffu, rs1, 2);
        if ((lane & 3) == 0) { rsum[wn*64 + row0] = rs0; rsum[wn*64 + row1] = rs1; }
        __syncthreads();   // Ps complete + rsums visible
        l_r[0] = l_r[0] * corr0 + rsum[row0] + rsum[64 + row0];
        l_r[1] = l_r[1] * corr1 + rsum[row1] + rsum[64 + row1];

        // O = O*corr + P V   (warp: m16 x n64, 4 k16 steps)
        #pragma unroll
        for (int nt = 0; nt < 8; nt++) {
            o[nt][0] *= corr0; o[nt][1] *= corr0;
            o[nt][2] *= corr1; o[nt][3] *= corr1;
        }
        #pragma unroll
        for (int ks = 0; ks < 4; ks++) {
            unsigned pa[4];
            {
                uint32_t row = wm * 16 + (lane & 15);
                uint32_t c = ks * 2 + (lane >> 4);
                LDSM4(pa, sb + AT_PS + offN(row, 128, c));
            }
            #pragma unroll
            for (int nb = 0; nb < 4; nb++) {
                unsigned vb[4];
                uint32_t row = ks * 16 + (lane & 7) + (((lane >> 3) & 1) << 3);
                uint32_t c = wn * 8 + nb * 2 + (lane >> 4);
                LDSM4T(vb, sb + AT_VS + offN(row, 256, c));
                MMA16(o[nb*2],   pa, vb[0], vb[1]);
                MMA16(o[nb*2+1], pa, vb[2], vb[3]);
            }
        }
    }

    // epilogue
    float inv0 = 1.0f / l_r[0], inv1 = 1.0f / l_r[1];
    #pragma unroll
    for (int nt = 0; nt < 8; nt++) {
        int d = wn * 64 + nt * 8 + (lane & 3) * 2;
        size_t r0 = (base + q0 + row0) * (size_t)(NH_*DV_) + h*DV_ + d;
        size_t r1 = (base + q0 + row1) * (size_t)(NH_*DV_) + h*DV_ + d;
        *(float2*)&AO[r0] = make_float2(o[nt][0]*inv0, o[nt][1]*inv0);
        *(float2*)&AO[r1] = make_float2(o[nt][2]*inv1, o[nt][3]*inv1);
    }
}

// ---------------------------------------------------------------------------
extern "C" void kernel_launch(void* const* d_in, const int* in_sizes, int n_in,
                              void* d_out, int out_size) {
    const float* hidden = (const float*)d_in[0];
    const float* q_w    = (const float*)d_in[2];
    const float* kv_a_w = (const float*)d_in[3];
    const float* ln_w   = (const float*)d_in[4];
    const float* kv_b_w = (const float*)d_in[5];
    const float* o_w    = (const float*)d_in[6];
    float*       out    = (float*)d_out;

    float *pQ, *pCKV, *pCLN, *pKV, *pKPE, *pAO;
    cudaGetSymbolAddress((void**)&pQ,   g_Q);
    cudaGetSymbolAddress((void**)&pCKV, g_CKV);
    cudaGetSymbolAddress((void**)&pCLN, g_CLN);
    cudaGetSymbolAddress((void**)&pKV,  g_KV);
    cudaGetSymbolAddress((void**)&pKPE, g_KPE);
    cudaGetSymbolAddress((void**)&pAO,  g_AO);

    cudaFuncSetAttribute(attn_fp16, cudaFuncAttributeMaxDynamicSharedMemorySize,
                         (int)ATTN_SMEM);

    dim3 blk(256);
    // 1. Q projection: [4096,2048] x [3072,2048]^T
    gemm_fp16<<<dim3(NQ_/128, M_/128), blk>>>(hidden, q_w, pQ, M_, NQ_, HID_);
    // 2. KV-A projection: [4096,2048] x [576,2048]^T (5 n-blocks, last partial)
    gemm_fp16<<<dim3((CKVW_+127)/128, M_/128), blk>>>(hidden, kv_a_w, pCKV, M_, CKVW_, HID_);
    // 3. RMSNorm on c
    rmsnorm_k<<<M_, 128>>>(pCKV, ln_w, pCLN);
    // 4. KV-B projection: [4096,512] x [4096,512]^T
    gemm_fp16<<<dim3(NKV_/128, M_/128), blk>>>(pCLN, kv_b_w, pKV, M_, NKV_, RANK_);
    // 5/6. RoPE
    rope_q<<<(M_*NH_)/8, 256>>>(pQ);
    rope_k<<<M_/8, 256>>>(pCKV, pKPE);
    // 7. Attention
    attn_fp16<<<dim3(S_/64, NH_, B_), blk, ATTN_SMEM>>>(pQ, pKV, pKPE, pAO);
    // 8. Output projection -> d_out
    gemm_fp16<<<dim3(HID_/128, M_/128), blk>>>(pAO, o_w, out, M_, HID_, HID_);
}